// round 9
// baseline (speedup 1.0000x reference)
#include <cuda_runtime.h>
#include <math.h>

#define BSZ       512
#define NODES     1000
#define HALF      500
#define DIM       128
#define NB_HEADS  8
#define EMB3      384          // DIM * 3 layers, row stride of K_att / V_att
#define HSTR      501          // smem stride for half-node arrays

// Scratch (allocation-free). Double-buffered by layer; flags zeroed per replay.
__device__ int   g_flag[3][BSZ];
__device__ float g_partV[2][BSZ][2][DIM];       // unnormalized sum_n e*V
__device__ float g_esum[2][BSZ][2][NB_HEADS];   // sum_n e per head
__device__ float g_denom[BSZ][2];               // final-layer denominators

__global__ void init_flags()
{
    int i = blockIdx.x * blockDim.x + threadIdx.x;
    if (i < 3 * BSZ) ((int*)g_flag)[i] = 0;
}

// ---------------------------------------------------------------------------
// Mask: runtime layout detection (uint8 / int32 / float32), decode half-row.
// ---------------------------------------------------------------------------
__device__ __forceinline__ void load_mask_half(const void* mask, int b, int base,
                                               int tid, unsigned char* smask)
{
    const unsigned char* p = (const unsigned char*)mask;
    bool viol_i32 = false, viol_f32 = false;
    {
        unsigned char b0 = p[4 * tid + 0];
        unsigned char b1 = p[4 * tid + 1];
        unsigned char b2 = p[4 * tid + 2];
        unsigned char b3 = p[4 * tid + 3];
        viol_i32 = (b1 | b2 | b3) != 0;
        bool zero = (b0 | b1 | b2 | b3) == 0;
        bool one  = (b0 == 0 && b1 == 0 && b2 == 0x80 && b3 == 0x3f);
        viol_f32 = !(zero || one);
    }
    const int any_i32_viol = __syncthreads_or(viol_i32);
    const int any_f32_viol = __syncthreads_or(viol_f32);

    if (!any_i32_viol) {
        const int* mi = (const int*)mask + (size_t)b * NODES + base;
        for (int n = tid; n < HALF; n += 256) smask[n] = (mi[n] != 0);
    } else if (!any_f32_viol) {
        const float* mf = (const float*)mask + (size_t)b * NODES + base;
        for (int n = tid; n < HALF; n += 256) smask[n] = (mf[n] != 0.0f);
    } else {
        const unsigned char* mu = (const unsigned char*)mask + (size_t)b * NODES + base;
        for (int n = tid; n < HALF; n += 256) smask[n] = (mu[n] != 0);
    }
    __syncthreads();
}

// Pairwise sibling sync on row b, stage l. Both blocks co-resident (grid 1024
// <= 148 SMs * 8 blocks), so spinning is deadlock-free.
__device__ __forceinline__ void pair_sync(int l, int b, int tid)
{
    __syncthreads();
    if (tid == 0) {
        __threadfence();                       // release our scratch writes
        atomicAdd(&g_flag[l][b], 1);
        while (atomicAdd(&g_flag[l][b], 0) != 2) __nanosleep(64);
    }
    __syncthreads();                           // all threads see completion
}

// dst = src @ Ww^T + Wb (128x128); one thread per output element.
__device__ __forceinline__ void linear128(int tid,
                                          const float* __restrict__ Ww,
                                          const float* __restrict__ Wb,
                                          const float* src, float* dst)
{
    if (tid < DIM) {
        float r = Wb[tid];
        const float* Wr = Ww + tid * DIM;
        #pragma unroll 8
        for (int k = 0; k < DIM; k++) r += __ldg(Wr + k) * src[k];
        dst[tid] = r;
    }
    __syncthreads();
}

// ---------------------------------------------------------------------------
// Fused 3-layer kernel, half-row granularity. grid = 1024 (b = bid>>1,
// half = bid&1), 256 threads = 8 warps, 8 blocks/SM -> all co-resident.
// ---------------------------------------------------------------------------
__global__ __launch_bounds__(256, 8)
void decoder_fused(const float* __restrict__ K_att,
                   const float* __restrict__ V_att,
                   const void*  __restrict__ mask,
                   const float* __restrict__ query0,
                   const float* __restrict__ W0w,
                   const float* __restrict__ W0b,
                   const float* __restrict__ Wqw,
                   const float* __restrict__ Wqb,
                   float* __restrict__ out)
{
    __shared__ __align__(16) float sq[DIM];
    __shared__ float slog[NB_HEADS * HSTR];        // e weights / dot partials (16 KB)
    __shared__ float ssum[8][NB_HEADS];
    __shared__ __align__(16) float spart[8][DIM];  // per-warp e*V partials (4 KB)
    __shared__ float scomb[DIM];
    __shared__ float sexp[HALF];                   // final-layer exp values (2 KB)
    __shared__ float sreds[8];
    __shared__ unsigned char smask[HALF];

    const int bid  = blockIdx.x;
    const int b    = bid >> 1;
    const int half = bid & 1;
    const int base = half * HALF;
    const int tid  = threadIdx.x;
    const int lane = tid & 31;
    const int warp = tid >> 5;

    load_mask_half(mask, b, base, tid, smask);

    if (tid < DIM) sq[tid] = query0[b * DIM + tid];
    __syncthreads();

    const float* Krow = K_att + (size_t)b * NODES * EMB3 + (size_t)base * EMB3;
    const float* Vrow = V_att + (size_t)b * NODES * EMB3 + (size_t)base * EMB3;

    // ======================= Layers 0 and 1 (8-head MHA) ====================
    #pragma unroll 1
    for (int layer = 0; layer < 2; layer++) {
        const float4 q4 = reinterpret_cast<const float4*>(sq)[lane];
        const float* Kb = Krow + layer * DIM;
        const float* Vb = Vrow + layer * DIM;

        // ---- Phase A: K stream -> e weights + per-head denominators -------
        {
            float es = 0.f;                 // valid on lanes with (lane&3)==0
            for (int n0 = warp * 4; n0 + 3 < HALF; n0 += 32) {
                float4 k[4];
                #pragma unroll
                for (int i = 0; i < 4; i++)
                    k[i] = __ldg(reinterpret_cast<const float4*>(Kb + (size_t)(n0 + i) * EMB3) + lane);
                #pragma unroll
                for (int i = 0; i < 4; i++) {
                    float p = k[i].x * q4.x + k[i].y * q4.y + k[i].z * q4.z + k[i].w * q4.w;
                    p += __shfl_xor_sync(0xffffffffu, p, 1);
                    p += __shfl_xor_sync(0xffffffffu, p, 2);
                    if ((lane & 3) == 0) {
                        const int n = n0 + i;
                        float e = smask[n] ? 0.f : __expf(p * 0.25f);   // 1/sqrt(16)
                        slog[(lane >> 2) * HSTR + n] = e;
                        es += e;
                    }
                }
            }
            if ((lane & 3) == 0) ssum[warp][lane >> 2] = es;
        }
        __syncthreads();

        // ---- Phase B: V stream, warp-per-node --------------------------------
        {
            const float* Lh = slog + (lane >> 2) * HSTR;
            float4 acc = make_float4(0.f, 0.f, 0.f, 0.f);
            int n = warp;
            for (; n + 24 < HALF; n += 32) {
                float4 v[4];
                #pragma unroll
                for (int i = 0; i < 4; i++)
                    v[i] = __ldg(reinterpret_cast<const float4*>(Vb + (size_t)(n + 8 * i) * EMB3) + lane);
                #pragma unroll
                for (int i = 0; i < 4; i++) {
                    const float w = Lh[n + 8 * i];
                    acc.x += w * v[i].x; acc.y += w * v[i].y;
                    acc.z += w * v[i].z; acc.w += w * v[i].w;
                }
            }
            for (; n < HALF; n += 8) {
                float4 v0 = __ldg(reinterpret_cast<const float4*>(Vb + (size_t)n * EMB3) + lane);
                const float w = Lh[n];
                acc.x += w * v0.x; acc.y += w * v0.y; acc.z += w * v0.z; acc.w += w * v0.w;
            }
            reinterpret_cast<float4*>(spart[warp])[lane] = acc;
        }
        __syncthreads();

        // ---- Publish partials, sync with sibling, combine, apply W0 --------
        if (tid < DIM) {
            float r = 0.f;
            #pragma unroll
            for (int w = 0; w < 8; w++) r += spart[w][tid];
            g_partV[layer][b][half][tid] = r;
        }
        if (tid >= DIM && tid < DIM + NB_HEADS) {
            const int h = tid - DIM;
            float s = 0.f;
            #pragma unroll
            for (int w = 0; w < 8; w++) s += ssum[w][h];
            g_esum[layer][b][half][h] = s;
        }
        pair_sync(layer, b, tid);

        if (tid < DIM) {
            const int h = tid >> 4;
            const float inv = 1.0f / (__ldcg(&g_esum[layer][b][0][h]) +
                                      __ldcg(&g_esum[layer][b][1][h]));
            scomb[tid] = (__ldcg(&g_partV[layer][b][0][tid]) +
                          __ldcg(&g_partV[layer][b][1][tid])) * inv;
        }
        __syncthreads();
        linear128(tid, W0w, W0b, scomb, sq);   // query after this layer
    }

    // q_final = query @ Wq^T + Wqb
    linear128(tid, Wqw, Wqb, sq, scomb);
    if (tid < DIM) sq[tid] = scomb[tid];
    __syncthreads();

    // ======================= Final layer (1 head, clip) =====================
    {
        const float4 q4 = reinterpret_cast<const float4*>(sq)[lane];
        const float* Kb = Krow + 2 * DIM;

        for (int n0 = warp * 4; n0 + 3 < HALF; n0 += 32) {
            float4 k[4];
            #pragma unroll
            for (int i = 0; i < 4; i++)
                k[i] = __ldg(reinterpret_cast<const float4*>(Kb + (size_t)(n0 + i) * EMB3) + lane);
            #pragma unroll
            for (int i = 0; i < 4; i++) {
                float p = k[i].x * q4.x + k[i].y * q4.y + k[i].z * q4.z + k[i].w * q4.w;
                p += __shfl_xor_sync(0xffffffffu, p, 1);
                p += __shfl_xor_sync(0xffffffffu, p, 2);
                if ((lane & 3) == 0) slog[(lane >> 2) * HSTR + (n0 + i)] = p;
            }
        }
        __syncthreads();

        // exp(clip(logit)); |logit| <= 10 (tanh clip) -> no max pass needed.
        const float scale = 0.0883883476483184f;   // 1/sqrt(128)
        float s = 0.f;
        for (int n = tid; n < HALF; n += 256) {
            float d = 0.f;
            #pragma unroll
            for (int h = 0; h < NB_HEADS; h++) d += slog[h * HSTR + n];
            float e = smask[n] ? 0.f : __expf(10.0f * tanhf(d * scale));
            sexp[n] = e;
            s += e;
        }
        #pragma unroll
        for (int o = 16; o; o >>= 1) s += __shfl_xor_sync(0xffffffffu, s, o);
        if (lane == 0) sreds[warp] = s;
        __syncthreads();
        if (tid == 0) {
            float ss = 0.f;
            #pragma unroll
            for (int w = 0; w < 8; w++) ss += sreds[w];
            g_denom[b][half] = ss;
        }
        pair_sync(2, b, tid);

        const float inv = 1.0f / (__ldcg(&g_denom[b][0]) + __ldcg(&g_denom[b][1]));
        float* ob = out + (size_t)b * NODES + base;
        for (int n = tid; n < HALF; n += 256) ob[n] = sexp[n] * inv;
    }
}

// ---------------------------------------------------------------------------
extern "C" void kernel_launch(void* const* d_in, const int* in_sizes, int n_in,
                              void* d_out, int out_size)
{
    const float* query = (const float*)d_in[0];
    const float* K_att = (const float*)d_in[1];
    const float* V_att = (const float*)d_in[2];
    const void*  mask  = d_in[3];
    const float* W0w   = (const float*)d_in[4];
    const float* W0b   = (const float*)d_in[5];
    const float* Wqw   = (const float*)d_in[6];
    const float* Wqb   = (const float*)d_in[7];
    float* out = (float*)d_out;

    init_flags   <<<3, 512>>>();
    decoder_fused<<<2 * BSZ, 256>>>(K_att, V_att, mask, query,
                                    W0w, W0b, Wqw, Wqb, out);
}

// round 10
// speedup vs baseline: 1.5315x; 1.5315x over previous
#include <cuda_runtime.h>
#include <math.h>

#define BSZ       512
#define NODES     1000
#define DIM       128
#define NB_HEADS  8
#define EMB3      384          // DIM * 3 layers, row stride of K_att / V_att
#define LSTR      1001         // smem stride

// Intermediate query buffers (device scratch; allocation-free per harness rules)
__device__ float g_q[2][BSZ * DIM];

// ---------------------------------------------------------------------------
// Decode mask row for batch b into smask[0..NODES) with runtime layout
// detection (uint8 / int32 / float32), voted once per block.
// ---------------------------------------------------------------------------
__device__ __forceinline__ void load_mask_row(const void* mask, int b, int tid,
                                              unsigned char* smask)
{
    const unsigned char* p = (const unsigned char*)mask;
    bool viol_i32 = false, viol_f32 = false;
    if (tid < 256) {
        unsigned char b0 = p[4 * tid + 0];
        unsigned char b1 = p[4 * tid + 1];
        unsigned char b2 = p[4 * tid + 2];
        unsigned char b3 = p[4 * tid + 3];
        viol_i32 = (b1 | b2 | b3) != 0;
        bool zero = (b0 | b1 | b2 | b3) == 0;
        bool one  = (b0 == 0 && b1 == 0 && b2 == 0x80 && b3 == 0x3f);
        viol_f32 = !(zero || one);
    }
    const int any_i32_viol = __syncthreads_or(viol_i32);
    const int any_f32_viol = __syncthreads_or(viol_f32);

    if (!any_i32_viol) {
        const int* mi = (const int*)mask + (size_t)b * NODES;
        for (int n = tid; n < NODES; n += blockDim.x) smask[n] = (mi[n] != 0);
    } else if (!any_f32_viol) {
        const float* mf = (const float*)mask + (size_t)b * NODES;
        for (int n = tid; n < NODES; n += blockDim.x) smask[n] = (mf[n] != 0.0f);
    } else {
        const unsigned char* mu = (const unsigned char*)mask + (size_t)b * NODES;
        for (int n = tid; n < NODES; n += blockDim.x) smask[n] = (mu[n] != 0);
    }
    __syncthreads();
}

// ---------------------------------------------------------------------------
// Compact unmasked node indices (deterministic, ascending). Warp 0 scans.
// Masked nodes have softmax weight exactly 0 (exp(-1e9-m) underflows), so
// their K and V rows need never be touched.
// ---------------------------------------------------------------------------
__device__ __forceinline__ int compact_indices(const unsigned char* smask,
                                               int* sidx, int* sM,
                                               int tid, int lane, int warp)
{
    if (warp == 0) {
        int base = 0;
        for (int n0 = 0; n0 < NODES; n0 += 32) {
            const int n = n0 + lane;
            const bool keep = (n < NODES) && !smask[n];
            const unsigned bal = __ballot_sync(0xffffffffu, keep);
            if (keep) sidx[base + __popc(bal & ((1u << lane) - 1u))] = n;
            base += __popc(bal);
        }
        if (lane == 0) *sM = base;
    }
    __syncthreads();
    return *sM;
}

// ---------------------------------------------------------------------------
// Layers 0 and 1: 8-head MHA over unmasked nodes + fused 128x128 linear (W0).
// One block per batch row, 512 threads = 16 warps. Phase A gathers K rows of
// unmasked nodes (4 in flight), computes e = exp(logit) directly (no max
// pass; logits O(5), softmax shift-invariant) and per-warp denominators.
// Phase B gathers V rows weighted by e.
// ---------------------------------------------------------------------------
__global__ __launch_bounds__(512, 4)
void attn_layer01(const float* __restrict__ K_att,
                  const float* __restrict__ V_att,
                  const void*  __restrict__ mask,
                  const float* __restrict__ query0,
                  const float* __restrict__ W0w,
                  const float* __restrict__ W0b,
                  int layer)
{
    __shared__ __align__(16) float sq[DIM];
    __shared__ float slog[NB_HEADS * LSTR];         // e weights at compacted j (32 KB)
    __shared__ float ssum[16][NB_HEADS];
    __shared__ float sinv[NB_HEADS];
    __shared__ __align__(16) float spart[16][DIM];  // per-warp e*V partials (8 KB)
    __shared__ float sout[DIM];
    __shared__ unsigned char smask[NODES];
    __shared__ int sidx[NODES];
    __shared__ int sM;

    const int b    = blockIdx.x;
    const int tid  = threadIdx.x;
    const int lane = tid & 31;
    const int warp = tid >> 5;

    load_mask_row(mask, b, tid, smask);
    const int M = compact_indices(smask, sidx, &sM, tid, lane, warp);

    const float* qin = (layer == 0) ? (query0 + b * DIM) : (g_q[0] + b * DIM);
    if (tid < DIM) sq[tid] = qin[tid];
    __syncthreads();

    const float4 q4 = reinterpret_cast<const float4*>(sq)[lane];
    const float* Kb = K_att + (size_t)b * NODES * EMB3 + layer * DIM;
    const float* Vb = V_att + (size_t)b * NODES * EMB3 + layer * DIM;

    // ---- Phase A: gathered K stream -> e weights + denominators -----------
    {
        float es = 0.f;                 // valid on lanes with (lane&3)==0
        for (int j0 = warp * 4; j0 < M; j0 += 64) {
            float4 k[4];
            #pragma unroll
            for (int i = 0; i < 4; i++) {
                if (j0 + i < M)
                    k[i] = __ldg(reinterpret_cast<const float4*>(
                               Kb + (size_t)sidx[j0 + i] * EMB3) + lane);
            }
            #pragma unroll
            for (int i = 0; i < 4; i++) {
                if (j0 + i < M) {
                    float p = k[i].x * q4.x + k[i].y * q4.y + k[i].z * q4.z + k[i].w * q4.w;
                    p += __shfl_xor_sync(0xffffffffu, p, 1);
                    p += __shfl_xor_sync(0xffffffffu, p, 2);
                    if ((lane & 3) == 0) {
                        float e = __expf(p * 0.25f);   // 1/sqrt(16)
                        slog[(lane >> 2) * LSTR + (j0 + i)] = e;
                        es += e;
                    }
                }
            }
        }
        if ((lane & 3) == 0) ssum[warp][lane >> 2] = es;
    }
    __syncthreads();

    if (tid < NB_HEADS) {
        float s = 0.f;
        #pragma unroll
        for (int w = 0; w < 16; w++) s += ssum[w][tid];
        sinv[tid] = 1.0f / s;
    }

    // ---- Phase B: gathered V stream, warp-per-node, 4 loads in flight ------
    {
        const float* Lh = slog + (lane >> 2) * LSTR;
        float4 acc = make_float4(0.f, 0.f, 0.f, 0.f);
        int j = warp;
        for (; j + 48 < M; j += 64) {
            float4 v[4];
            #pragma unroll
            for (int i = 0; i < 4; i++)
                v[i] = __ldg(reinterpret_cast<const float4*>(
                           Vb + (size_t)sidx[j + 16 * i] * EMB3) + lane);
            #pragma unroll
            for (int i = 0; i < 4; i++) {
                const float w = Lh[j + 16 * i];
                acc.x += w * v[i].x; acc.y += w * v[i].y;
                acc.z += w * v[i].z; acc.w += w * v[i].w;
            }
        }
        for (; j < M; j += 16) {
            float4 v0 = __ldg(reinterpret_cast<const float4*>(
                           Vb + (size_t)sidx[j] * EMB3) + lane);
            const float w = Lh[j];
            acc.x += w * v0.x; acc.y += w * v0.y; acc.z += w * v0.z; acc.w += w * v0.w;
        }
        reinterpret_cast<float4*>(spart[warp])[lane] = acc;
    }
    __syncthreads();

    if (tid < DIM) {
        float r = 0.f;
        #pragma unroll
        for (int w = 0; w < 16; w++) r += spart[w][tid];
        sout[tid] = r * sinv[tid >> 4];
    }
    __syncthreads();

    // ---- Fused linear: q_next = out @ W0w^T + W0b --------------------------
    if (tid < DIM) {
        float r = W0b[tid];
        const float* Wr = W0w + tid * DIM;
        #pragma unroll 8
        for (int k = 0; k < DIM; k++) r += Wr[k] * sout[k];
        g_q[layer][b * DIM + tid] = r;
    }
}

// ---------------------------------------------------------------------------
// Final layer: q = Wq q + b ; single-head logits with 10*tanh clip over
// unmasked nodes, softmax -> probabilities (masked outputs are exactly 0).
// Clip bounds logits to [-10,10] -> exp without max-subtraction is safe.
// ---------------------------------------------------------------------------
__global__ __launch_bounds__(512, 4)
void attn_final(const float* __restrict__ K_att,
                const void*  __restrict__ mask,
                const float* __restrict__ Wqw,
                const float* __restrict__ Wqb,
                float* __restrict__ out)
{
    __shared__ __align__(16) float sqin[DIM];
    __shared__ __align__(16) float sq[DIM];
    __shared__ float spartl[NB_HEADS * LSTR];   // dot partials at compacted j (32 KB)
    __shared__ float sexp[NODES];               // scattered exp values (4 KB)
    __shared__ float sreds[16];
    __shared__ unsigned char smask[NODES];
    __shared__ int sidx[NODES];
    __shared__ int sM;

    const int b    = blockIdx.x;
    const int tid  = threadIdx.x;
    const int lane = tid & 31;
    const int warp = tid >> 5;

    load_mask_row(mask, b, tid, smask);
    const int M = compact_indices(smask, sidx, &sM, tid, lane, warp);

    for (int n = tid; n < NODES; n += 512) sexp[n] = 0.f;

    if (tid < DIM) sqin[tid] = g_q[1][b * DIM + tid];
    __syncthreads();
    if (tid < DIM) {
        float r = Wqb[tid];
        const float* Wr = Wqw + tid * DIM;
        #pragma unroll 8
        for (int k = 0; k < DIM; k++) r += Wr[k] * sqin[k];
        sq[tid] = r;
    }
    __syncthreads();

    const float4 q4 = reinterpret_cast<const float4*>(sq)[lane];
    const float* Kb = K_att + (size_t)b * NODES * EMB3 + 2 * DIM;

    // Gathered K stream, 4 nodes per iter, 2-shuffle partials.
    for (int j0 = warp * 4; j0 < M; j0 += 64) {
        float4 k[4];
        #pragma unroll
        for (int i = 0; i < 4; i++) {
            if (j0 + i < M)
                k[i] = __ldg(reinterpret_cast<const float4*>(
                           Kb + (size_t)sidx[j0 + i] * EMB3) + lane);
        }
        #pragma unroll
        for (int i = 0; i < 4; i++) {
            if (j0 + i < M) {
                float p = k[i].x * q4.x + k[i].y * q4.y + k[i].z * q4.z + k[i].w * q4.w;
                p += __shfl_xor_sync(0xffffffffu, p, 1);
                p += __shfl_xor_sync(0xffffffffu, p, 2);
                if ((lane & 3) == 0) spartl[(lane >> 2) * LSTR + (j0 + i)] = p;
            }
        }
    }
    __syncthreads();

    // Combine partials -> exp(clip(logit)), scatter to node position.
    const float scale = 0.0883883476483184f;   // 1/sqrt(128)
    float s = 0.f;
    for (int j = tid; j < M; j += 512) {
        float d = 0.f;
        #pragma unroll
        for (int h = 0; h < NB_HEADS; h++) d += spartl[h * LSTR + j];
        float e = __expf(10.0f * tanhf(d * scale));
        sexp[sidx[j]] = e;
        s += e;
    }
    #pragma unroll
    for (int o = 16; o; o >>= 1) s += __shfl_xor_sync(0xffffffffu, s, o);
    if (lane == 0) sreds[warp] = s;
    __syncthreads();
    if (tid < 32) {
        float ss = (lane < 16) ? sreds[lane] : 0.f;
        #pragma unroll
        for (int o = 8; o; o >>= 1) ss += __shfl_xor_sync(0xffffffffu, ss, o);
        if (lane == 0) sreds[0] = ss;
    }
    __syncthreads();
    const float inv = 1.0f / sreds[0];

    float* ob = out + (size_t)b * NODES;
    for (int n = tid; n < NODES; n += 512) ob[n] = sexp[n] * inv;
}

// ---------------------------------------------------------------------------
extern "C" void kernel_launch(void* const* d_in, const int* in_sizes, int n_in,
                              void* d_out, int out_size)
{
    const float* query = (const float*)d_in[0];
    const float* K_att = (const float*)d_in[1];
    const float* V_att = (const float*)d_in[2];
    const void*  mask  = d_in[3];
    const float* W0w   = (const float*)d_in[4];
    const float* W0b   = (const float*)d_in[5];
    const float* Wqw   = (const float*)d_in[6];
    const float* Wqb   = (const float*)d_in[7];
    float* out = (float*)d_out;

    attn_layer01<<<BSZ, 512>>>(K_att, V_att, mask, query, W0w, W0b, 0);
    attn_layer01<<<BSZ, 512>>>(K_att, V_att, mask, query, W0w, W0b, 1);
    attn_final  <<<BSZ, 512>>>(K_att, mask, Wqw, Wqb, out);
}

// round 11
// speedup vs baseline: 1.6007x; 1.0452x over previous
#include <cuda_runtime.h>
#include <math.h>

#define BSZ       512
#define NODES     1000
#define DIM       128
#define NB_HEADS  8
#define EMB3      384          // DIM * 3 layers, row stride of K_att / V_att
#define LSTR      1065         // smem stride (>=1024+pad, 1065%32==9 -> conflict-free)
#define IPAD      1064         // sidx capacity (Mpad <= 1024)

// Intermediate query buffers (device scratch; allocation-free per harness rules)
__device__ float g_q[2][BSZ * DIM];

// ---------------------------------------------------------------------------
// Decode mask row for batch b into smask[0..NODES) with runtime layout
// detection (uint8 / int32 / float32), voted once per block.
// ---------------------------------------------------------------------------
__device__ __forceinline__ void load_mask_row(const void* mask, int b, int tid,
                                              unsigned char* smask)
{
    const unsigned char* p = (const unsigned char*)mask;
    bool viol_i32 = false, viol_f32 = false;
    if (tid < 256) {
        unsigned char b0 = p[4 * tid + 0];
        unsigned char b1 = p[4 * tid + 1];
        unsigned char b2 = p[4 * tid + 2];
        unsigned char b3 = p[4 * tid + 3];
        viol_i32 = (b1 | b2 | b3) != 0;
        bool zero = (b0 | b1 | b2 | b3) == 0;
        bool one  = (b0 == 0 && b1 == 0 && b2 == 0x80 && b3 == 0x3f);
        viol_f32 = !(zero || one);
    }
    const int any_i32_viol = __syncthreads_or(viol_i32);
    const int any_f32_viol = __syncthreads_or(viol_f32);

    if (!any_i32_viol) {
        const int* mi = (const int*)mask + (size_t)b * NODES;
        for (int n = tid; n < NODES; n += blockDim.x) smask[n] = (mi[n] != 0);
    } else if (!any_f32_viol) {
        const float* mf = (const float*)mask + (size_t)b * NODES;
        for (int n = tid; n < NODES; n += blockDim.x) smask[n] = (mf[n] != 0.0f);
    } else {
        const unsigned char* mu = (const unsigned char*)mask + (size_t)b * NODES;
        for (int n = tid; n < NODES; n += blockDim.x) smask[n] = (mu[n] != 0);
    }
    __syncthreads();
}

// ---------------------------------------------------------------------------
// Compact unmasked node indices (deterministic, ascending), pad to a multiple
// of 64 with a valid index (node 0 is always unmasked in this dataset; even
// if not, padded slots carry zero weight). Returns M (real count); *sMp gets
// Mpad. Masked nodes have softmax weight exactly 0 (exp(-1e9-m) underflows),
// so their K and V rows are never touched.
// ---------------------------------------------------------------------------
__device__ __forceinline__ void compact_indices(const unsigned char* smask,
                                                int* sidx, int* sMM,
                                                int tid, int lane, int warp)
{
    if (warp == 0) {
        int base = 0;
        for (int n0 = 0; n0 < NODES; n0 += 32) {
            const int n = n0 + lane;
            const bool keep = (n < NODES) && !smask[n];
            const unsigned bal = __ballot_sync(0xffffffffu, keep);
            if (keep) sidx[base + __popc(bal & ((1u << lane) - 1u))] = n;
            base += __popc(bal);
        }
        const int M    = base;
        const int Mpad = (M + 63) & ~63;
        const int fill = sidx[0];
        for (int j = M + lane; j < Mpad; j += 32) sidx[j] = fill;
        if (lane == 0) { sMM[0] = M; sMM[1] = Mpad; }
    }
    __syncthreads();
}

// ---------------------------------------------------------------------------
// Layers 0 and 1: 8-head MHA over unmasked nodes + fused 128x128 linear (W0).
// One block per batch row, 512 threads = 16 warps. All gather loads are
// UNGUARDED (padded index array) so ptxas batches 4 LDGs per iteration.
// exp without max pass (logits O(5), softmax shift-invariant).
// ---------------------------------------------------------------------------
__global__ __launch_bounds__(512, 4)
void attn_layer01(const float* __restrict__ K_att,
                  const float* __restrict__ V_att,
                  const void*  __restrict__ mask,
                  const float* __restrict__ query0,
                  const float* __restrict__ W0w,
                  const float* __restrict__ W0b,
                  int layer)
{
    __shared__ __align__(16) float sq[DIM];
    __shared__ float slog[NB_HEADS * LSTR];         // e weights at compacted j (34 KB)
    __shared__ float ssum[16][NB_HEADS];
    __shared__ float sinv[NB_HEADS];
    __shared__ __align__(16) float spart[16][DIM];  // per-warp e*V partials (8 KB)
    __shared__ float sout[DIM];
    __shared__ unsigned char smask[NODES];
    __shared__ int sidx[IPAD];
    __shared__ int sMM[2];

    const int b    = blockIdx.x;
    const int tid  = threadIdx.x;
    const int lane = tid & 31;
    const int warp = tid >> 5;

    load_mask_row(mask, b, tid, smask);
    compact_indices(smask, sidx, sMM, tid, lane, warp);
    const int M    = sMM[0];
    const int Mpad = sMM[1];

    const float* qin = (layer == 0) ? (query0 + b * DIM) : (g_q[0] + b * DIM);
    if (tid < DIM) sq[tid] = qin[tid];
    __syncthreads();

    const float4 q4 = reinterpret_cast<const float4*>(sq)[lane];
    const float* Kb = K_att + (size_t)b * NODES * EMB3 + layer * DIM;
    const float* Vb = V_att + (size_t)b * NODES * EMB3 + layer * DIM;

    // ---- Phase A: gathered K stream (unguarded loads) ----------------------
    {
        float es = 0.f;                 // valid on lanes with (lane&3)==0
        for (int j0 = warp * 4; j0 < Mpad; j0 += 64) {
            int idx[4];
            #pragma unroll
            for (int i = 0; i < 4; i++) idx[i] = sidx[j0 + i];
            float4 k[4];
            #pragma unroll
            for (int i = 0; i < 4; i++)
                k[i] = __ldg(reinterpret_cast<const float4*>(Kb + (size_t)idx[i] * EMB3) + lane);
            #pragma unroll
            for (int i = 0; i < 4; i++) {
                float p = k[i].x * q4.x + k[i].y * q4.y + k[i].z * q4.z + k[i].w * q4.w;
                p += __shfl_xor_sync(0xffffffffu, p, 1);
                p += __shfl_xor_sync(0xffffffffu, p, 2);
                if ((lane & 3) == 0) {
                    const float e = (j0 + i < M) ? __expf(p * 0.25f) : 0.f;  // 1/sqrt(16)
                    slog[(lane >> 2) * LSTR + (j0 + i)] = e;
                    es += e;
                }
            }
        }
        if ((lane & 3) == 0) ssum[warp][lane >> 2] = es;
    }
    __syncthreads();

    if (tid < NB_HEADS) {
        float s = 0.f;
        #pragma unroll
        for (int w = 0; w < 16; w++) s += ssum[w][tid];
        sinv[tid] = 1.0f / s;
    }

    // ---- Phase B: gathered V stream (unguarded; padded weights are 0) ------
    {
        const float* Lh = slog + (lane >> 2) * LSTR;
        float4 acc = make_float4(0.f, 0.f, 0.f, 0.f);
        for (int j = warp; j < Mpad; j += 64) {
            int idx[4];
            #pragma unroll
            for (int i = 0; i < 4; i++) idx[i] = sidx[j + 16 * i];
            float4 v[4];
            #pragma unroll
            for (int i = 0; i < 4; i++)
                v[i] = __ldg(reinterpret_cast<const float4*>(Vb + (size_t)idx[i] * EMB3) + lane);
            #pragma unroll
            for (int i = 0; i < 4; i++) {
                const float w = Lh[j + 16 * i];
                acc.x += w * v[i].x; acc.y += w * v[i].y;
                acc.z += w * v[i].z; acc.w += w * v[i].w;
            }
        }
        reinterpret_cast<float4*>(spart[warp])[lane] = acc;
    }
    __syncthreads();

    if (tid < DIM) {
        float r = 0.f;
        #pragma unroll
        for (int w = 0; w < 16; w++) r += spart[w][tid];
        sout[tid] = r * sinv[tid >> 4];
    }
    __syncthreads();

    // ---- Fused linear: q_next = out @ W0w^T + W0b --------------------------
    if (tid < DIM) {
        float r = W0b[tid];
        const float* Wr = W0w + tid * DIM;
        #pragma unroll 8
        for (int k = 0; k < DIM; k++) r += Wr[k] * sout[k];
        g_q[layer][b * DIM + tid] = r;
    }
}

// ---------------------------------------------------------------------------
// Final layer: q = Wq q + b ; single-head logits with 10*tanh clip over
// unmasked nodes, softmax -> probabilities (masked outputs exactly 0).
// Clip bounds logits to [-10,10] -> exp without max-subtraction is safe.
// ---------------------------------------------------------------------------
__global__ __launch_bounds__(512, 4)
void attn_final(const float* __restrict__ K_att,
                const void*  __restrict__ mask,
                const float* __restrict__ Wqw,
                const float* __restrict__ Wqb,
                float* __restrict__ out)
{
    __shared__ __align__(16) float sqin[DIM];
    __shared__ __align__(16) float sq[DIM];
    __shared__ float spartl[NB_HEADS * LSTR];   // dot partials at compacted j (34 KB)
    __shared__ float sexp[NODES];               // scattered exp values (4 KB)
    __shared__ float sreds[16];
    __shared__ unsigned char smask[NODES];
    __shared__ int sidx[IPAD];
    __shared__ int sMM[2];

    const int b    = blockIdx.x;
    const int tid  = threadIdx.x;
    const int lane = tid & 31;
    const int warp = tid >> 5;

    load_mask_row(mask, b, tid, smask);
    compact_indices(smask, sidx, sMM, tid, lane, warp);
    const int M    = sMM[0];
    const int Mpad = sMM[1];

    for (int n = tid; n < NODES; n += 512) sexp[n] = 0.f;

    if (tid < DIM) sqin[tid] = g_q[1][b * DIM + tid];
    __syncthreads();
    if (tid < DIM) {
        float r = Wqb[tid];
        const float* Wr = Wqw + tid * DIM;
        #pragma unroll 8
        for (int k = 0; k < DIM; k++) r += Wr[k] * sqin[k];
        sq[tid] = r;
    }
    __syncthreads();

    const float4 q4 = reinterpret_cast<const float4*>(sq)[lane];
    const float* Kb = K_att + (size_t)b * NODES * EMB3 + 2 * DIM;

    // Gathered K stream (unguarded loads), 2-shuffle partials.
    for (int j0 = warp * 4; j0 < Mpad; j0 += 64) {
        int idx[4];
        #pragma unroll
        for (int i = 0; i < 4; i++) idx[i] = sidx[j0 + i];
        float4 k[4];
        #pragma unroll
        for (int i = 0; i < 4; i++)
            k[i] = __ldg(reinterpret_cast<const float4*>(Kb + (size_t)idx[i] * EMB3) + lane);
        #pragma unroll
        for (int i = 0; i < 4; i++) {
            float p = k[i].x * q4.x + k[i].y * q4.y + k[i].z * q4.z + k[i].w * q4.w;
            p += __shfl_xor_sync(0xffffffffu, p, 1);
            p += __shfl_xor_sync(0xffffffffu, p, 2);
            if ((lane & 3) == 0) spartl[(lane >> 2) * LSTR + (j0 + i)] = p;
        }
    }
    __syncthreads();

    // Combine partials -> exp(clip(logit)), scatter to node position.
    const float scale = 0.0883883476483184f;   // 1/sqrt(128)
    float s = 0.f;
    for (int j = tid; j < M; j += 512) {
        float d = 0.f;
        #pragma unroll
        for (int h = 0; h < NB_HEADS; h++) d += spartl[h * LSTR + j];
        float e = __expf(10.0f * tanhf(d * scale));
        sexp[sidx[j]] = e;
        s += e;
    }
    #pragma unroll
    for (int o = 16; o; o >>= 1) s += __shfl_xor_sync(0xffffffffu, s, o);
    if (lane == 0) sreds[warp] = s;
    __syncthreads();
    if (tid < 32) {
        float ss = (lane < 16) ? sreds[lane] : 0.f;
        #pragma unroll
        for (int o = 8; o; o >>= 1) ss += __shfl_xor_sync(0xffffffffu, ss, o);
        if (lane == 0) sreds[0] = ss;
    }
    __syncthreads();
    const float inv = 1.0f / sreds[0];

    float* ob = out + (size_t)b * NODES;
    for (int n = tid; n < NODES; n += 512) ob[n] = sexp[n] * inv;
}

// ---------------------------------------------------------------------------
extern "C" void kernel_launch(void* const* d_in, const int* in_sizes, int n_in,
                              void* d_out, int out_size)
{
    const float* query = (const float*)d_in[0];
    const float* K_att = (const float*)d_in[1];
    const float* V_att = (const float*)d_in[2];
    const void*  mask  = d_in[3];
    const float* W0w   = (const float*)d_in[4];
    const float* W0b   = (const float*)d_in[5];
    const float* Wqw   = (const float*)d_in[6];
    const float* Wqb   = (const float*)d_in[7];
    float* out = (float*)d_out;

    attn_layer01<<<BSZ, 512>>>(K_att, V_att, mask, query, W0w, W0b, 0);
    attn_layer01<<<BSZ, 512>>>(K_att, V_att, mask, query, W0w, W0b, 1);
    attn_final  <<<BSZ, 512>>>(K_att, mask, Wqw, Wqb, out);
}